// round 13
// baseline (speedup 1.0000x reference)
#include <cuda_runtime.h>

#define N_VOX 1000000
#define KVOL  27
#define C_IN  3
#define C_HID 64
#define C_OUT 3
#define BN_EPS 1e-5f
#define PBLK  128   // points per block; 64 pairs; warp handles 8 pairs
#define NPAIR (PBLK/2)
#define IDMASK 0x1FFFFFF
#define VBIT  (1 << 30)
#define FULLM 0xffffffffu

// Scratch (device globals: allocation-free per harness rules)
__device__ float g_h[(size_t)N_VOX * C_HID];   // 256 MB: conv1 out (pre-BN)
__device__ float g_stats[4 * C_HID];           // sum, sumsq, scale, shift

typedef unsigned long long u64;

__device__ __forceinline__ u64 pack2(float lo, float hi) {
    u64 r; asm("mov.b64 %0, {%1, %2};" : "=l"(r) : "f"(lo), "f"(hi)); return r;
}
__device__ __forceinline__ void unpack2(u64 v, float& lo, float& hi) {
    asm("mov.b64 {%0, %1}, %2;" : "=f"(lo), "=f"(hi) : "l"(v));
}
#define FMA2(d, a, b, c) asm("fma.rn.f32x2 %0, %1, %2, %3;" : "=l"(d) : "l"(a), "l"(b), "l"(c))

__device__ __forceinline__ u64 relu2(u64 v) {
    float a, b; unpack2(v, a, b);
    return pack2(fmaxf(a, 0.f), fmaxf(b, 0.f));
}

// ---------------------------------------------------------------------------
__global__ void zero_stats_kernel() {
    int i = threadIdx.x;
    if (i < 2 * C_HID) g_stats[i] = 0.f;
}
__global__ void dummy_kernel() {}   // keeps conv1 at ncu capture index 3

// ---------------------------------------------------------------------------
// conv1 (pair teams, MERGED k-union lists):
// Per pair, a single list over the union of the two points' valid offsets;
// entry j carries k (5 bits), valid bit, id — so BOTH 16-lane halves process
// the SAME k at step j and each weight LDS.128 covers 256B unique (2 wf, was 4).
// Batch shfl gather as R12. Fused BN-stats.
__global__ __launch_bounds__(256, 6) void conv1_kernel(const float* __restrict__ feats,
                                                       const float* __restrict__ W1,
                                                       const int*   __restrict__ nbr) {
    __shared__ ulonglong2 w1p[KVOL * 48];       // 20.7 KB  [(k*3+c)*16 + tl]
    __shared__ int lstA[NPAIR][KVOL];           // 6.9 KB
    __shared__ int lstB[NPAIR][KVOL];           // 6.9 KB
    __shared__ int cntsU[NPAIR];
    __shared__ float st_sm[2 * C_HID];
    const int tid = threadIdx.x;
    {
        const u64* w1g = (const u64*)W1;        // pair index = (k*3+c)*32 + p
        for (int i = tid; i < KVOL * 48; i += 256) {
            int kc = i >> 4, t = i & 15;
            int b = kc * 32 + 2 * t;
            w1p[i] = make_ulonglong2(w1g[b], w1g[b + 1]);
        }
    }
    if (tid < 2 * C_HID) st_sm[tid] = 0.f;
    const int base = blockIdx.x * PBLK;
    if (tid < NPAIR) {                          // merged-list staging (uniform k loop)
        const int pr = tid;
        const int nA = base + 2 * pr, nB = nA + 1;
        int c = 0;
        #pragma unroll 1
        for (int k = 0; k < KVOL; k++) {
            int idA = (nA < N_VOX) ? __ldg(&nbr[(size_t)k * N_VOX + nA]) : -1;
            int idB = (nB < N_VOX) ? __ldg(&nbr[(size_t)k * N_VOX + nB]) : -1;
            if ((idA >= 0) || (idB >= 0)) {
                lstA[pr][c] = (k << 25) | (idA >= 0 ? (VBIT | idA) : 0);
                lstB[pr][c] = (k << 25) | (idB >= 0 ? (VBIT | idB) : 0);
                c++;
            }
        }
        cntsU[pr] = c;
    }
    __syncthreads();

    const int lane   = tid & 31;
    const int wrp    = tid >> 5;
    const int tlane  = lane & 15;
    const int half16 = lane & 16;

    float s0 = 0.f, s1 = 0.f, s2v = 0.f, s3 = 0.f;
    float q0 = 0.f, q1 = 0.f, q2 = 0.f, q3 = 0.f;

    #pragma unroll 1
    for (int pp = 0; pp < 8; pp++) {            // 8 pairs per warp
        const int pr = wrp * 8 + pp;
        const int n  = base + 2 * pr + (half16 >> 4);
        const int cntU = cntsU[pr];

        u64 acc0 = 0ull, acc1 = 0ull;           // lane's channels 4t..4t+3
        #pragma unroll 1
        for (int b = 0; b < cntU; b += 16) {
            int j = b + tlane;
            int e = 0;
            if (j < cntU) e = half16 ? lstB[pr][j] : lstA[pr][j];
            int kk = (e >> 25) & 31;
            float f0 = 0.f, f1 = 0.f, f2 = 0.f;
            if (e & VBIT) {                     // 16-wide parallel gather
                int id = e & IDMASK;
                f0 = __ldg(&feats[3 * id + 0]);
                f1 = __ldg(&feats[3 * id + 1]);
                f2 = __ldg(&feats[3 * id + 2]);
            }
            const int nb = min(cntU - b, 16);
            #pragma unroll 1
            for (int jj = 0; jj < nb; jj++) {   // convergent; same k both halves
                int srcl = half16 + jj;
                int k    = __shfl_sync(FULLM, kk, srcl);
                float e0 = __shfl_sync(FULLM, f0, srcl);
                float e1 = __shfl_sync(FULLM, f1, srcl);
                float e2 = __shfl_sync(FULLM, f2, srcl);
                const ulonglong2* wp = w1p + k * 48 + tlane;   // mirrored halves
                ulonglong2 w0 = wp[0], w1v = wp[16], w2v = wp[32];
                u64 a0 = pack2(e0, e0), a1 = pack2(e1, e1), a2 = pack2(e2, e2);
                FMA2(acc0, a0, w0.x,  acc0); FMA2(acc1, a0, w0.y,  acc1);
                FMA2(acc0, a1, w1v.x, acc0); FMA2(acc1, a1, w1v.y, acc1);
                FMA2(acc0, a2, w2v.x, acc0); FMA2(acc1, a2, w2v.y, acc1);
            }
        }
        if (n < N_VOX) {
            ulonglong2* ho = (ulonglong2*)(g_h + (size_t)n * C_HID) + tlane;
            *ho = make_ulonglong2(acc0, acc1);
            float h0, h1, h2, h3;
            unpack2(acc0, h0, h1);
            unpack2(acc1, h2, h3);
            s0 += h0; s1 += h1; s2v += h2; s3 += h3;
            q0 = fmaf(h0, h0, q0); q1 = fmaf(h1, h1, q1);
            q2 = fmaf(h2, h2, q2); q3 = fmaf(h3, h3, q3);
        }
    }

    atomicAdd(&st_sm[4 * tlane + 0], s0);
    atomicAdd(&st_sm[4 * tlane + 1], s1);
    atomicAdd(&st_sm[4 * tlane + 2], s2v);
    atomicAdd(&st_sm[4 * tlane + 3], s3);
    atomicAdd(&st_sm[C_HID + 4 * tlane + 0], q0);
    atomicAdd(&st_sm[C_HID + 4 * tlane + 1], q1);
    atomicAdd(&st_sm[C_HID + 4 * tlane + 2], q2);
    atomicAdd(&st_sm[C_HID + 4 * tlane + 3], q3);
    __syncthreads();
    if (tid < 2 * C_HID) atomicAdd(&g_stats[tid], st_sm[tid]);
}

// ---------------------------------------------------------------------------
__global__ void finalize_kernel(const float* __restrict__ gamma,
                                const float* __restrict__ beta) {
    int d = threadIdx.x;
    if (d < C_HID) {
        float mu  = g_stats[d] * (1.f / N_VOX);
        float var = g_stats[C_HID + d] * (1.f / N_VOX) - mu * mu;
        float sc  = gamma[d] * rsqrtf(var + BN_EPS);
        g_stats[2 * C_HID + d] = sc;
        g_stats[3 * C_HID + d] = beta[d] - mu * sc;
    }
}

// ---------------------------------------------------------------------------
// conv2 (pair teams, MERGED k-union lists): out[n] = sum_k relu(bn(h[nbr])) @ W2t
// Same k both halves -> mirrored weight LDS (2 wf). Predicated h-gather;
// invalid halves zeroed AFTER bn+relu (relu(shift) != 0 in general).
__global__ __launch_bounds__(256, 6) void conv2_kernel(const float* __restrict__ W2,
                                                       const int*   __restrict__ nbr,
                                                       float* __restrict__ out) {
    __shared__ ulonglong2 w2p[KVOL * 48];       // plane: [(k*3+c)*16 + tl]
    __shared__ int lstA[NPAIR][KVOL];
    __shared__ int lstB[NPAIR][KVOL];
    __shared__ int cntsU[NPAIR];
    const int tid = threadIdx.x;
    {
        // wt[k][c][d] = W2[26-k][d][c]; lane tl gets channels 4tl..4tl+3
        float* fp = (float*)w2p;
        for (int i = tid; i < KVOL * C_OUT * C_HID; i += 256) {
            int k   = i / (C_OUT * C_HID);
            int rem = i % (C_OUT * C_HID);
            int c   = rem / C_HID;
            int d   = rem % C_HID;
            float v = W2[(size_t)(KVOL - 1 - k) * (C_HID * C_OUT) + d * C_OUT + c];
            int t = d >> 2, j = d & 3;
            fp[((k * 3 + c) * 16 + t) * 4 + j] = v;
        }
    }
    const int base = blockIdx.x * PBLK;
    if (tid < NPAIR) {
        const int pr = tid;
        const int nA = base + 2 * pr, nB = nA + 1;
        int c = 0;
        #pragma unroll 1
        for (int k = 0; k < KVOL; k++) {
            int idA = (nA < N_VOX) ? __ldg(&nbr[(size_t)k * N_VOX + nA]) : -1;
            int idB = (nB < N_VOX) ? __ldg(&nbr[(size_t)k * N_VOX + nB]) : -1;
            if ((idA >= 0) || (idB >= 0)) {
                lstA[pr][c] = (k << 25) | (idA >= 0 ? (VBIT | idA) : 0);
                lstB[pr][c] = (k << 25) | (idB >= 0 ? (VBIT | idB) : 0);
                c++;
            }
        }
        cntsU[pr] = c;
    }
    __syncthreads();

    const int lane   = tid & 31;
    const int wrp    = tid >> 5;
    const int tlane  = lane & 15;
    const int half16 = lane & 16;

    const u64 scA = pack2(g_stats[2 * C_HID + 4 * tlane + 0], g_stats[2 * C_HID + 4 * tlane + 1]);
    const u64 scB = pack2(g_stats[2 * C_HID + 4 * tlane + 2], g_stats[2 * C_HID + 4 * tlane + 3]);
    const u64 shA = pack2(g_stats[3 * C_HID + 4 * tlane + 0], g_stats[3 * C_HID + 4 * tlane + 1]);
    const u64 shB = pack2(g_stats[3 * C_HID + 4 * tlane + 2], g_stats[3 * C_HID + 4 * tlane + 3]);

    #pragma unroll 1
    for (int pp = 0; pp < 8; pp++) {            // 8 pairs per warp
        const int pr = wrp * 8 + pp;
        const int n  = base + 2 * pr + (half16 >> 4);
        const int cntU = cntsU[pr];

        u64 acc0 = 0ull, acc1 = 0ull, acc2 = 0ull;
        #pragma unroll 2
        for (int j = 0; j < cntU; j++) {
            int e = half16 ? lstB[pr][j] : lstA[pr][j];
            int k = (e >> 25) & 31;
            bool v = (e & VBIT) != 0;
            ulonglong2 hv = make_ulonglong2(0ull, 0ull);
            if (v) {
                int id = e & IDMASK;
                hv = __ldg((const ulonglong2*)(g_h + (size_t)id * C_HID) + tlane);
            }
            FMA2(hv.x, hv.x, scA, shA);
            FMA2(hv.y, hv.y, scB, shB);
            hv.x = relu2(hv.x);
            hv.y = relu2(hv.y);
            if (!v) { hv.x = 0ull; hv.y = 0ull; }   // relu(shift) must not leak
            const ulonglong2* wp = w2p + k * 48 + tlane;   // mirrored halves
            ulonglong2 w0 = wp[0], w1 = wp[16], w2v = wp[32];
            FMA2(acc0, hv.x, w0.x,  acc0); FMA2(acc0, hv.y, w0.y,  acc0);
            FMA2(acc1, hv.x, w1.x,  acc1); FMA2(acc1, hv.y, w1.y,  acc1);
            FMA2(acc2, hv.x, w2v.x, acc2); FMA2(acc2, hv.y, w2v.y, acc2);
        }
        float r0, r1, r2;
        { float lo, hi; unpack2(acc0, lo, hi); r0 = lo + hi; }
        { float lo, hi; unpack2(acc1, lo, hi); r1 = lo + hi; }
        { float lo, hi; unpack2(acc2, lo, hi); r2 = lo + hi; }
        #pragma unroll
        for (int o = 8; o >= 1; o >>= 1) {
            r0 += __shfl_xor_sync(FULLM, r0, o);
            r1 += __shfl_xor_sync(FULLM, r1, o);
            r2 += __shfl_xor_sync(FULLM, r2, o);
        }
        if (tlane == 0 && n < N_VOX) {
            out[3 * n + 0] = r0;
            out[3 * n + 1] = r1;
            out[3 * n + 2] = r2;
        }
    }
}

// ---------------------------------------------------------------------------
extern "C" void kernel_launch(void* const* d_in, const int* in_sizes, int n_in,
                              void* d_out, int out_size) {
    const float* feats = (const float*)d_in[0];
    const float* W1    = (const float*)d_in[1];
    const float* gamma = (const float*)d_in[2];
    const float* beta  = (const float*)d_in[3];
    const float* W2    = (const float*)d_in[4];
    const int*   nbr   = (const int*)  d_in[5];
    float*       out   = (float*)d_out;

    const int nblk = (N_VOX + PBLK - 1) / PBLK;

    zero_stats_kernel<<<1, 128>>>();                    // 0
    dummy_kernel<<<1, 32>>>();                          // 1
    dummy_kernel<<<1, 32>>>();                          // 2
    conv1_kernel<<<nblk, 256>>>(feats, W1, nbr);        // 3 <- ncu
    finalize_kernel<<<1, 64>>>(gamma, beta);            // 4
    conv2_kernel<<<nblk, 256>>>(W2, nbr, out);          // 5
}

// round 14
// speedup vs baseline: 1.0855x; 1.0855x over previous
#include <cuda_runtime.h>

#define N_VOX 1000000
#define KVOL  27
#define C_IN  3
#define C_HID 64
#define C_OUT 3
#define BN_EPS 1e-5f
#define PBLK  128   // points per block; 64 pairs; warp handles 8 pairs
#define NPAIR (PBLK/2)
#define IDMASK 0x1FFFFFF
#define VBIT  (1 << 30)
#define FULLM 0xffffffffu

// Scratch (device globals: allocation-free per harness rules)
__device__ float g_h[(size_t)N_VOX * C_HID];   // 256 MB: conv1 out (pre-BN)
__device__ float g_stats[4 * C_HID];           // sum, sumsq, scale, shift

typedef unsigned long long u64;

__device__ __forceinline__ u64 pack2(float lo, float hi) {
    u64 r; asm("mov.b64 %0, {%1, %2};" : "=l"(r) : "f"(lo), "f"(hi)); return r;
}
__device__ __forceinline__ void unpack2(u64 v, float& lo, float& hi) {
    asm("mov.b64 {%0, %1}, %2;" : "=f"(lo), "=f"(hi) : "l"(v));
}
#define FMA2(d, a, b, c) asm("fma.rn.f32x2 %0, %1, %2, %3;" : "=l"(d) : "l"(a), "l"(b), "l"(c))

__device__ __forceinline__ u64 relu2(u64 v) {
    float a, b; unpack2(v, a, b);
    return pack2(fmaxf(a, 0.f), fmaxf(b, 0.f));
}

// ---------------------------------------------------------------------------
__global__ void zero_stats_kernel() {
    int i = threadIdx.x;
    if (i < 2 * C_HID) g_stats[i] = 0.f;
}
__global__ void dummy_kernel() {}   // keeps conv1 at ncu capture index 3

// ---------------------------------------------------------------------------
// conv1 (pair teams, merged k-union via parallel staging + byte k-list):
// h[n,:] = sum_{valid k} feats[nbr[k,n]] @ W1[k]
// Staging: 256-thread coalesced nbr LDGs fill lstA/lstB[pair][k] and a union
// bitmask (smem atomicOr). 64-thread smem-only pass compacts masks into byte
// lists lstK. Hot loop: batch-shfl (R12) with SAME k in both halves ->
// mirrored LDS.128 weight reads = 2 wavefronts (halved). Fused BN-stats.
__global__ __launch_bounds__(256, 6) void conv1_kernel(const float* __restrict__ feats,
                                                       const float* __restrict__ W1,
                                                       const int*   __restrict__ nbr) {
    __shared__ ulonglong2 w1p[KVOL * 48];        // 20.7 KB [(k*3+c)*16 + tl]
    __shared__ int lstA[NPAIR][KVOL];            // 6.9 KB  VBIT|id per (pair,k)
    __shared__ int lstB[NPAIR][KVOL];            // 6.9 KB
    __shared__ unsigned mskS[NPAIR];
    __shared__ unsigned char lstK[NPAIR][28];    // 1.8 KB  compact k order
    __shared__ int cnts[NPAIR];
    __shared__ float st_sm[2 * C_HID];
    const int tid = threadIdx.x;

    // phase 0: weights + zeroing
    {
        const u64* w1g = (const u64*)W1;         // pair index = (k*3+c)*32 + p
        for (int i = tid; i < KVOL * 48; i += 256) {
            int kc = i >> 4, t = i & 15;
            int b = kc * 32 + 2 * t;
            w1p[i] = make_ulonglong2(w1g[b], w1g[b + 1]);
        }
    }
    if (tid < NPAIR) mskS[tid] = 0;
    if (tid < 2 * C_HID) st_sm[tid] = 0.f;
    __syncthreads();

    // phase 1: cooperative coalesced staging
    const int base = blockIdx.x * PBLK;
    for (int i = tid; i < KVOL * PBLK; i += 256) {
        int k = i >> 7, pl = i & 127;
        int n = base + pl;
        int id = (n < N_VOX) ? __ldg(&nbr[(size_t)k * N_VOX + n]) : -1;
        int pr = pl >> 1;
        int pk = (id >= 0) ? (VBIT | id) : 0;
        if (pl & 1) lstB[pr][k] = pk; else lstA[pr][k] = pk;
        if (id >= 0) atomicOr(&mskS[pr], 1u << k);
    }
    __syncthreads();

    // phase 2: smem-only mask compaction (no LDGs)
    if (tid < NPAIR) {
        unsigned m = mskS[tid];
        int c = 0;
        while (m) {
            int k = __ffs(m) - 1;
            m &= m - 1;
            lstK[tid][c++] = (unsigned char)k;
        }
        cnts[tid] = c;
    }
    __syncthreads();

    const int lane   = tid & 31;
    const int wrp    = tid >> 5;
    const int tlane  = lane & 15;
    const int half16 = lane & 16;
    const int (*lstH)[KVOL] = half16 ? lstB : lstA;   // uniform per thread

    float s0 = 0.f, s1 = 0.f, s2v = 0.f, s3 = 0.f;
    float q0 = 0.f, q1 = 0.f, q2 = 0.f, q3 = 0.f;

    #pragma unroll 1
    for (int pp = 0; pp < 8; pp++) {             // 8 pairs per warp
        const int pr = wrp * 8 + pp;
        const int n  = base + 2 * pr + (half16 >> 4);
        const int cntU = cnts[pr];

        u64 acc0 = 0ull, acc1 = 0ull;            // lane's channels 4t..4t+3
        #pragma unroll 1
        for (int b = 0; b < cntU; b += 16) {
            int j = b + tlane;
            int kk = 0, e = 0;
            float f0 = 0.f, f1 = 0.f, f2 = 0.f;
            if (j < cntU) {
                kk = lstK[pr][j];
                e  = lstH[pr][kk];
            }
            if (e & VBIT) {                      // 16-wide parallel gather
                int id = e & IDMASK;
                f0 = __ldg(&feats[3 * id + 0]);
                f1 = __ldg(&feats[3 * id + 1]);
                f2 = __ldg(&feats[3 * id + 2]);
            }
            const int nb = min(cntU - b, 16);
            #pragma unroll 1
            for (int jj = 0; jj < nb; jj++) {    // convergent; same k both halves
                int srcl = half16 + jj;
                int k    = __shfl_sync(FULLM, kk, srcl);
                float e0 = __shfl_sync(FULLM, f0, srcl);
                float e1 = __shfl_sync(FULLM, f1, srcl);
                float e2 = __shfl_sync(FULLM, f2, srcl);
                const ulonglong2* wp = w1p + k * 48 + tlane;   // mirrored halves
                ulonglong2 w0 = wp[0], w1v = wp[16], w2v = wp[32];
                u64 a0 = pack2(e0, e0), a1 = pack2(e1, e1), a2 = pack2(e2, e2);
                FMA2(acc0, a0, w0.x,  acc0); FMA2(acc1, a0, w0.y,  acc1);
                FMA2(acc0, a1, w1v.x, acc0); FMA2(acc1, a1, w1v.y, acc1);
                FMA2(acc0, a2, w2v.x, acc0); FMA2(acc1, a2, w2v.y, acc1);
            }
        }
        if (n < N_VOX) {
            ulonglong2* ho = (ulonglong2*)(g_h + (size_t)n * C_HID) + tlane;
            *ho = make_ulonglong2(acc0, acc1);
            float h0, h1, h2, h3;
            unpack2(acc0, h0, h1);
            unpack2(acc1, h2, h3);
            s0 += h0; s1 += h1; s2v += h2; s3 += h3;
            q0 = fmaf(h0, h0, q0); q1 = fmaf(h1, h1, q1);
            q2 = fmaf(h2, h2, q2); q3 = fmaf(h3, h3, q3);
        }
    }

    atomicAdd(&st_sm[4 * tlane + 0], s0);
    atomicAdd(&st_sm[4 * tlane + 1], s1);
    atomicAdd(&st_sm[4 * tlane + 2], s2v);
    atomicAdd(&st_sm[4 * tlane + 3], s3);
    atomicAdd(&st_sm[C_HID + 4 * tlane + 0], q0);
    atomicAdd(&st_sm[C_HID + 4 * tlane + 1], q1);
    atomicAdd(&st_sm[C_HID + 4 * tlane + 2], q2);
    atomicAdd(&st_sm[C_HID + 4 * tlane + 3], q3);
    __syncthreads();
    if (tid < 2 * C_HID) atomicAdd(&g_stats[tid], st_sm[tid]);
}

// ---------------------------------------------------------------------------
__global__ void finalize_kernel(const float* __restrict__ gamma,
                                const float* __restrict__ beta) {
    int d = threadIdx.x;
    if (d < C_HID) {
        float mu  = g_stats[d] * (1.f / N_VOX);
        float var = g_stats[C_HID + d] * (1.f / N_VOX) - mu * mu;
        float sc  = gamma[d] * rsqrtf(var + BN_EPS);
        g_stats[2 * C_HID + d] = sc;
        g_stats[3 * C_HID + d] = beta[d] - mu * sc;
    }
}

// ---------------------------------------------------------------------------
// conv2 (pair teams, merged k-union, parallel staging):
// out[n] = sum_k relu(bn(h[nbr[k,n]])) @ W2[26-k]
// Same k both halves -> mirrored weight LDS (2 wf). Predicated h-gather;
// invalid halves zeroed AFTER bn+relu (relu(shift) != 0 in general).
__global__ __launch_bounds__(256, 6) void conv2_kernel(const float* __restrict__ W2,
                                                       const int*   __restrict__ nbr,
                                                       float* __restrict__ out) {
    __shared__ ulonglong2 w2p[KVOL * 48];        // plane: [(k*3+c)*16 + tl]
    __shared__ int lstA[NPAIR][KVOL];
    __shared__ int lstB[NPAIR][KVOL];
    __shared__ unsigned mskS[NPAIR];
    __shared__ unsigned char lstK[NPAIR][28];
    __shared__ int cnts[NPAIR];
    const int tid = threadIdx.x;
    {
        // wt[k][c][d] = W2[26-k][d][c]; lane tl gets channels 4tl..4tl+3
        float* fp = (float*)w2p;
        for (int i = tid; i < KVOL * C_OUT * C_HID; i += 256) {
            int k   = i / (C_OUT * C_HID);
            int rem = i % (C_OUT * C_HID);
            int c   = rem / C_HID;
            int d   = rem % C_HID;
            float v = W2[(size_t)(KVOL - 1 - k) * (C_HID * C_OUT) + d * C_OUT + c];
            int t = d >> 2, j = d & 3;
            fp[((k * 3 + c) * 16 + t) * 4 + j] = v;
        }
    }
    if (tid < NPAIR) mskS[tid] = 0;
    __syncthreads();

    const int base = blockIdx.x * PBLK;
    for (int i = tid; i < KVOL * PBLK; i += 256) {
        int k = i >> 7, pl = i & 127;
        int n = base + pl;
        int id = (n < N_VOX) ? __ldg(&nbr[(size_t)k * N_VOX + n]) : -1;
        int pr = pl >> 1;
        int pk = (id >= 0) ? (VBIT | id) : 0;
        if (pl & 1) lstB[pr][k] = pk; else lstA[pr][k] = pk;
        if (id >= 0) atomicOr(&mskS[pr], 1u << k);
    }
    __syncthreads();
    if (tid < NPAIR) {
        unsigned m = mskS[tid];
        int c = 0;
        while (m) {
            int k = __ffs(m) - 1;
            m &= m - 1;
            lstK[tid][c++] = (unsigned char)k;
        }
        cnts[tid] = c;
    }
    __syncthreads();

    const int lane   = tid & 31;
    const int wrp    = tid >> 5;
    const int tlane  = lane & 15;
    const int half16 = lane & 16;
    const int (*lstH)[KVOL] = half16 ? lstB : lstA;

    const u64 scA = pack2(g_stats[2 * C_HID + 4 * tlane + 0], g_stats[2 * C_HID + 4 * tlane + 1]);
    const u64 scB = pack2(g_stats[2 * C_HID + 4 * tlane + 2], g_stats[2 * C_HID + 4 * tlane + 3]);
    const u64 shA = pack2(g_stats[3 * C_HID + 4 * tlane + 0], g_stats[3 * C_HID + 4 * tlane + 1]);
    const u64 shB = pack2(g_stats[3 * C_HID + 4 * tlane + 2], g_stats[3 * C_HID + 4 * tlane + 3]);

    #pragma unroll 1
    for (int pp = 0; pp < 8; pp++) {             // 8 pairs per warp
        const int pr = wrp * 8 + pp;
        const int n  = base + 2 * pr + (half16 >> 4);
        const int cntU = cnts[pr];

        u64 acc0 = 0ull, acc1 = 0ull, acc2 = 0ull;
        #pragma unroll 2
        for (int j = 0; j < cntU; j++) {
            int k = lstK[pr][j];
            int e = lstH[pr][k];
            bool v = (e & VBIT) != 0;
            ulonglong2 hv = make_ulonglong2(0ull, 0ull);
            if (v) {
                int id = e & IDMASK;
                hv = __ldg((const ulonglong2*)(g_h + (size_t)id * C_HID) + tlane);
            }
            FMA2(hv.x, hv.x, scA, shA);
            FMA2(hv.y, hv.y, scB, shB);
            hv.x = relu2(hv.x);
            hv.y = relu2(hv.y);
            if (!v) { hv.x = 0ull; hv.y = 0ull; }   // relu(shift) must not leak
            const ulonglong2* wp = w2p + k * 48 + tlane;   // mirrored halves
            ulonglong2 w0 = wp[0], w1 = wp[16], w2v = wp[32];
            FMA2(acc0, hv.x, w0.x,  acc0); FMA2(acc0, hv.y, w0.y,  acc0);
            FMA2(acc1, hv.x, w1.x,  acc1); FMA2(acc1, hv.y, w1.y,  acc1);
            FMA2(acc2, hv.x, w2v.x, acc2); FMA2(acc2, hv.y, w2v.y, acc2);
        }
        float r0, r1, r2;
        { float lo, hi; unpack2(acc0, lo, hi); r0 = lo + hi; }
        { float lo, hi; unpack2(acc1, lo, hi); r1 = lo + hi; }
        { float lo, hi; unpack2(acc2, lo, hi); r2 = lo + hi; }
        #pragma unroll
        for (int o = 8; o >= 1; o >>= 1) {
            r0 += __shfl_xor_sync(FULLM, r0, o);
            r1 += __shfl_xor_sync(FULLM, r1, o);
            r2 += __shfl_xor_sync(FULLM, r2, o);
        }
        if (tlane == 0 && n < N_VOX) {
            out[3 * n + 0] = r0;
            out[3 * n + 1] = r1;
            out[3 * n + 2] = r2;
        }
    }
}

// ---------------------------------------------------------------------------
extern "C" void kernel_launch(void* const* d_in, const int* in_sizes, int n_in,
                              void* d_out, int out_size) {
    const float* feats = (const float*)d_in[0];
    const float* W1    = (const float*)d_in[1];
    const float* gamma = (const float*)d_in[2];
    const float* beta  = (const float*)d_in[3];
    const float* W2    = (const float*)d_in[4];
    const int*   nbr   = (const int*)  d_in[5];
    float*       out   = (float*)d_out;

    const int nblk = (N_VOX + PBLK - 1) / PBLK;

    zero_stats_kernel<<<1, 128>>>();                    // 0
    dummy_kernel<<<1, 32>>>();                          // 1
    dummy_kernel<<<1, 32>>>();                          // 2
    conv1_kernel<<<nblk, 256>>>(feats, W1, nbr);        // 3 <- ncu
    finalize_kernel<<<1, 64>>>(gamma, beta);            // 4
    conv2_kernel<<<nblk, 256>>>(W2, nbr, out);          // 5
}